// round 3
// baseline (speedup 1.0000x reference)
#include <cuda_runtime.h>
#include <cstdint>

#define NNODES 50000
#define EMAX   800000
#define DOUT   256
#define DIN    256

// Scratch (device globals — no allocation allowed)
__device__ float g_h[(size_t)NNODES * DOUT];   // x @ W
__device__ int   g_degi[NNODES];
__device__ int   g_off[NNODES];                // exclusive prefix (start of node's edges)
__device__ int   g_cur[NNODES];                // fill cursor
__device__ float g_dinv[NNODES];
__device__ int   g_csr[EMAX];                  // src node per edge, grouped by dst

// ---------------------------------------------------------------------------
__global__ void k_zero(int n) {
    int i = blockIdx.x * blockDim.x + threadIdx.x;
    if (i < n) g_degi[i] = 0;
}

__global__ void k_count(const int* __restrict__ dst, int E) {
    int i = blockIdx.x * blockDim.x + threadIdx.x;
    if (i < E) atomicAdd(&g_degi[dst[i]], 1);
}

__global__ void k_dinv(int n) {
    int i = blockIdx.x * blockDim.x + threadIdx.x;
    if (i < n) g_dinv[i] = rsqrtf((float)(g_degi[i] + 1));   // + self-loop
}

// Single-block exclusive scan over g_degi -> g_off, g_cur (warp-shuffle scan)
__global__ __launch_bounds__(1024) void k_scan(int n) {
    __shared__ int wsum[32];
    __shared__ int carry_s;
    int tid = threadIdx.x, lane = tid & 31, wid = tid >> 5;
    if (tid == 0) carry_s = 0;
    __syncthreads();
    for (int base = 0; base < n; base += 1024) {
        int i = base + tid;
        int v = (i < n) ? g_degi[i] : 0;
        int sc = v;
        #pragma unroll
        for (int o = 1; o < 32; o <<= 1) {
            int t = __shfl_up_sync(0xffffffffu, sc, o);
            if (lane >= o) sc += t;
        }
        if (lane == 31) wsum[wid] = sc;
        __syncthreads();
        if (wid == 0) {
            int s = wsum[lane];
            #pragma unroll
            for (int o = 1; o < 32; o <<= 1) {
                int t = __shfl_up_sync(0xffffffffu, s, o);
                if (lane >= o) s += t;
            }
            wsum[lane] = s;
        }
        __syncthreads();
        int warpoff = (wid > 0) ? wsum[wid - 1] : 0;
        int incl = carry_s + warpoff + sc;
        int excl = incl - v;
        if (i < n) { g_off[i] = excl; g_cur[i] = excl; }
        __syncthreads();
        if (tid == 1023) carry_s = incl;   // chunk total (pad lanes add 0)
        __syncthreads();
    }
}

__global__ void k_fill(const int* __restrict__ src,
                       const int* __restrict__ dst, int E) {
    int i = blockIdx.x * blockDim.x + threadIdx.x;
    if (i >= E) return;
    int d = dst[i];
    int pos = atomicAdd(&g_cur[d], 1);
    g_csr[pos] = src[i];
}

// ---------------------------------------------------------------------------
// GEMM: h[M,256] = x[M,256] @ W[256,256], fp32, 64x64 tile, BK=16
// ---------------------------------------------------------------------------
#define BM 64
#define BN 64
#define BK 16
__global__ __launch_bounds__(256) void k_gemm(const float* __restrict__ A,
                                              const float* __restrict__ B,
                                              int M) {
    __shared__ float As[BK][BM + 4];
    __shared__ float Bs[BK][BN + 4];

    const int tid = threadIdx.x;
    const int tx = tid % 16;
    const int ty = tid / 16;
    const int rowBase = blockIdx.y * BM;
    const int colBase = blockIdx.x * BN;

    float acc[4][4] = {};

    for (int k0 = 0; k0 < DIN; k0 += BK) {
        {
            int r = tid >> 2;
            int kk = (tid & 3) * 4;
            int gr = rowBase + r;
            float4 v = make_float4(0.f, 0.f, 0.f, 0.f);
            if (gr < M) v = *(const float4*)(A + (size_t)gr * DIN + k0 + kk);
            As[kk + 0][r] = v.x; As[kk + 1][r] = v.y;
            As[kk + 2][r] = v.z; As[kk + 3][r] = v.w;
        }
        {
            int kk = tid >> 4;
            int c  = (tid & 15) * 4;
            float4 v = *(const float4*)(B + (size_t)(k0 + kk) * DOUT + colBase + c);
            Bs[kk][c + 0] = v.x; Bs[kk][c + 1] = v.y;
            Bs[kk][c + 2] = v.z; Bs[kk][c + 3] = v.w;
        }
        __syncthreads();

        #pragma unroll
        for (int kk = 0; kk < BK; kk++) {
            float a[4], b[4];
            #pragma unroll
            for (int i = 0; i < 4; i++) a[i] = As[kk][ty * 4 + i];
            #pragma unroll
            for (int j = 0; j < 4; j++) b[j] = Bs[kk][tx * 4 + j];
            #pragma unroll
            for (int i = 0; i < 4; i++)
                #pragma unroll
                for (int j = 0; j < 4; j++)
                    acc[i][j] = fmaf(a[i], b[j], acc[i][j]);
        }
        __syncthreads();
    }

    #pragma unroll
    for (int i = 0; i < 4; i++) {
        int gr = rowBase + ty * 4 + i;
        if (gr >= M) continue;
        float* crow = g_h + (size_t)gr * DOUT + colBase + tx * 4;
        *(float4*)crow = make_float4(acc[i][0], acc[i][1], acc[i][2], acc[i][3]);
    }
}

// ---------------------------------------------------------------------------
// Node kernel: one warp per destination node.
// acc = sum_{e in CSR[node]} h[src_e]*dinv[src_e]
// y   = (acc + h[node]*dinv[node]) * dinv[node] + b  -> BN -> ReLU -> out
// ---------------------------------------------------------------------------
__global__ __launch_bounds__(256) void k_node(float* __restrict__ out,
                                              const float* __restrict__ b,
                                              const float* __restrict__ gamma,
                                              const float* __restrict__ beta,
                                              const float* __restrict__ mean,
                                              const float* __restrict__ var,
                                              int n) {
    int warp = (blockIdx.x * blockDim.x + threadIdx.x) >> 5;
    int lane = threadIdx.x & 31;
    if (warp >= n) return;

    int node = warp;
    int start = g_off[node];
    int end   = start + g_degi[node];

    float4 acc0 = make_float4(0.f, 0.f, 0.f, 0.f);
    float4 acc1 = make_float4(0.f, 0.f, 0.f, 0.f);

    int e = start;
    for (; e + 1 < end; e += 2) {
        int s0 = g_csr[e];
        int s1 = g_csr[e + 1];
        float w0 = g_dinv[s0];
        float w1 = g_dinv[s1];
        const float4* r0 = (const float4*)(g_h + (size_t)s0 * DOUT);
        const float4* r1 = (const float4*)(g_h + (size_t)s1 * DOUT);
        float4 a0 = r0[lane];
        float4 a1 = r0[lane + 32];
        float4 b0 = r1[lane];
        float4 b1 = r1[lane + 32];
        acc0.x = fmaf(a0.x, w0, acc0.x); acc0.y = fmaf(a0.y, w0, acc0.y);
        acc0.z = fmaf(a0.z, w0, acc0.z); acc0.w = fmaf(a0.w, w0, acc0.w);
        acc1.x = fmaf(a1.x, w0, acc1.x); acc1.y = fmaf(a1.y, w0, acc1.y);
        acc1.z = fmaf(a1.z, w0, acc1.z); acc1.w = fmaf(a1.w, w0, acc1.w);
        acc0.x = fmaf(b0.x, w1, acc0.x); acc0.y = fmaf(b0.y, w1, acc0.y);
        acc0.z = fmaf(b0.z, w1, acc0.z); acc0.w = fmaf(b0.w, w1, acc0.w);
        acc1.x = fmaf(b1.x, w1, acc1.x); acc1.y = fmaf(b1.y, w1, acc1.y);
        acc1.z = fmaf(b1.z, w1, acc1.z); acc1.w = fmaf(b1.w, w1, acc1.w);
    }
    if (e < end) {
        int s0 = g_csr[e];
        float w0 = g_dinv[s0];
        const float4* r0 = (const float4*)(g_h + (size_t)s0 * DOUT);
        float4 a0 = r0[lane];
        float4 a1 = r0[lane + 32];
        acc0.x = fmaf(a0.x, w0, acc0.x); acc0.y = fmaf(a0.y, w0, acc0.y);
        acc0.z = fmaf(a0.z, w0, acc0.z); acc0.w = fmaf(a0.w, w0, acc0.w);
        acc1.x = fmaf(a1.x, w0, acc1.x); acc1.y = fmaf(a1.y, w0, acc1.y);
        acc1.z = fmaf(a1.z, w0, acc1.z); acc1.w = fmaf(a1.w, w0, acc1.w);
    }

    // self-loop + outer dinv factor
    float di = g_dinv[node];
    const float4* hr = (const float4*)(g_h + (size_t)node * DOUT);
    float4 h0 = hr[lane];
    float4 h1 = hr[lane + 32];
    acc0.x = fmaf(h0.x, di, acc0.x); acc0.y = fmaf(h0.y, di, acc0.y);
    acc0.z = fmaf(h0.z, di, acc0.z); acc0.w = fmaf(h0.w, di, acc0.w);
    acc1.x = fmaf(h1.x, di, acc1.x); acc1.y = fmaf(h1.y, di, acc1.y);
    acc1.z = fmaf(h1.z, di, acc1.z); acc1.w = fmaf(h1.w, di, acc1.w);
    acc0.x *= di; acc0.y *= di; acc0.z *= di; acc0.w *= di;
    acc1.x *= di; acc1.y *= di; acc1.z *= di; acc1.w *= di;

    // bias + BN + ReLU; lane covers float4-channels lane and lane+32
    #pragma unroll
    for (int half = 0; half < 2; half++) {
        int c4 = lane + half * 32;
        float4 bv = ((const float4*)b)[c4];
        float4 gv = ((const float4*)gamma)[c4];
        float4 tv = ((const float4*)beta)[c4];
        float4 mv = ((const float4*)mean)[c4];
        float4 vv = ((const float4*)var)[c4];
        float4 a = half ? acc1 : acc0;
        float4 r;
        float sx = gv.x * rsqrtf(vv.x + 1e-5f);
        float sy = gv.y * rsqrtf(vv.y + 1e-5f);
        float sz = gv.z * rsqrtf(vv.z + 1e-5f);
        float sw = gv.w * rsqrtf(vv.w + 1e-5f);
        r.x = fmaxf(fmaf(a.x + bv.x - mv.x, sx, tv.x), 0.f);
        r.y = fmaxf(fmaf(a.y + bv.y - mv.y, sy, tv.y), 0.f);
        r.z = fmaxf(fmaf(a.z + bv.z - mv.z, sz, tv.z), 0.f);
        r.w = fmaxf(fmaf(a.w + bv.w - mv.w, sw, tv.w), 0.f);
        ((float4*)(out + (size_t)node * DOUT))[c4] = r;
    }
}

// ---------------------------------------------------------------------------
extern "C" void kernel_launch(void* const* d_in, const int* in_sizes, int n_in,
                              void* d_out, int out_size) {
    const float* x      = (const float*)d_in[0];
    const int*   ei     = (const int*)d_in[1];   // int32! jax x64 disabled
    const float* W      = (const float*)d_in[2];
    const float* b      = (const float*)d_in[3];
    const float* gamma  = (const float*)d_in[4];
    const float* beta   = (const float*)d_in[5];
    const float* rmean  = (const float*)d_in[6];
    const float* rvar   = (const float*)d_in[7];
    float* out = (float*)d_out;

    int N = in_sizes[0] / DIN;     // 50000
    int E = in_sizes[1] / 2;       // 800000
    const int* src = ei;
    const int* dst = ei + E;

    k_zero<<<(N + 255) / 256, 256>>>(N);
    k_count<<<(E + 255) / 256, 256>>>(dst, E);
    k_dinv<<<(N + 255) / 256, 256>>>(N);
    k_scan<<<1, 1024>>>(N);
    k_fill<<<(E + 255) / 256, 256>>>(src, dst, E);

    dim3 ggrid(DOUT / BN, (N + BM - 1) / BM);
    k_gemm<<<ggrid, 256>>>(x, W, N);

    long long nthreads = (long long)N * 32;
    k_node<<<(int)((nthreads + 255) / 256), 256>>>(out, b, gamma, beta,
                                                   rmean, rvar, N);
}

// round 5
// speedup vs baseline: 1.3638x; 1.3638x over previous
#include <cuda_runtime.h>
#include <cuda_bf16.h>
#include <mma.h>
#include <cstdint>

using namespace nvcuda;

#define NNODES 50000
#define MPAD   50048          // 391 * 128
#define EMAX   800000
#define DOUT   256
#define DIN    256

// ---------------------------------------------------------------------------
// Scratch (device globals)
// ---------------------------------------------------------------------------
__device__ float g_h[(size_t)MPAD * DOUT];       // x @ W (fp32, padded rows)
__device__ int   g_degi[NNODES];
__device__ int   g_off[NNODES];
__device__ int   g_cur[NNODES];
__device__ float g_dinv[NNODES];
__device__ int   g_csr[EMAX];
__device__ int   g_bsum[64];
__device__ __nv_bfloat16 g_a_hi[(size_t)MPAD * DIN];
__device__ __nv_bfloat16 g_a_lo[(size_t)MPAD * DIN];
__device__ __nv_bfloat16 g_wt_hi[DOUT * DIN];    // W^T [n][k], k contiguous
__device__ __nv_bfloat16 g_wt_lo[DOUT * DIN];

// ---------------------------------------------------------------------------
// Degree / CSR build
// ---------------------------------------------------------------------------
__global__ void k_zero(int n) {
    int i = blockIdx.x * blockDim.x + threadIdx.x;
    if (i < n) g_degi[i] = 0;
}
__global__ void k_count(const int* __restrict__ dst, int E) {
    int i = blockIdx.x * blockDim.x + threadIdx.x;
    if (i < E) atomicAdd(&g_degi[dst[i]], 1);
}

__global__ __launch_bounds__(1024) void k_scan1(int n) {
    __shared__ int wsum[32];
    int tid = threadIdx.x, lane = tid & 31, wid = tid >> 5;
    int i = blockIdx.x * 1024 + tid;
    int v = (i < n) ? g_degi[i] : 0;
    if (i < n) g_dinv[i] = rsqrtf((float)(v + 1));
    int sc = v;
    #pragma unroll
    for (int o = 1; o < 32; o <<= 1) {
        int t = __shfl_up_sync(0xffffffffu, sc, o);
        if (lane >= o) sc += t;
    }
    if (lane == 31) wsum[wid] = sc;
    __syncthreads();
    if (wid == 0) {
        int s = wsum[lane];
        #pragma unroll
        for (int o = 1; o < 32; o <<= 1) {
            int t = __shfl_up_sync(0xffffffffu, s, o);
            if (lane >= o) s += t;
        }
        wsum[lane] = s;
    }
    __syncthreads();
    int warpoff = (wid > 0) ? wsum[wid - 1] : 0;
    if (i < n) g_off[i] = warpoff + sc - v;
    if (tid == 0) g_bsum[blockIdx.x] = wsum[31];
}

__global__ void k_scan2(int nb) {
    __shared__ int w0tot;
    int t = threadIdx.x, lane = t & 31, wid = t >> 5;
    int v = (t < nb) ? g_bsum[t] : 0;
    int sc = v;
    #pragma unroll
    for (int o = 1; o < 32; o <<= 1) {
        int x = __shfl_up_sync(0xffffffffu, sc, o);
        if (lane >= o) sc += x;
    }
    if (wid == 0 && lane == 31) w0tot = sc;
    __syncthreads();
    int excl = sc - v + (wid ? w0tot : 0);
    if (t < nb) g_bsum[t] = excl;
}

__global__ __launch_bounds__(1024) void k_scan3(int n) {
    int i = blockIdx.x * 1024 + threadIdx.x;
    if (i >= n) return;
    int o = g_off[i] + g_bsum[blockIdx.x];
    g_off[i] = o;
    g_cur[i] = o;
}

__global__ void k_fill(const int* __restrict__ src,
                       const int* __restrict__ dst, int E) {
    int i = blockIdx.x * blockDim.x + threadIdx.x;
    if (i >= E) return;
    int d = dst[i];
    int pos = atomicAdd(&g_cur[d], 1);
    g_csr[pos] = src[i];
}

// ---------------------------------------------------------------------------
// Split prep
// ---------------------------------------------------------------------------
__device__ __forceinline__ uint32_t pack_hi2(float a, float b,
                                             __nv_bfloat16& ha, __nv_bfloat16& hb) {
    ha = __float2bfloat16_rn(a);
    hb = __float2bfloat16_rn(b);
    return ((uint32_t)__bfloat16_as_ushort(hb) << 16) | __bfloat16_as_ushort(ha);
}

// x -> g_a_hi/g_a_lo (rows >= M zero-filled). 8 bf16 per thread.
__global__ void k_split(const float* __restrict__ x, int M) {
    int i = blockIdx.x * blockDim.x + threadIdx.x;   // uint4 index (8 bf16)
    int total = MPAD * DIN / 8;
    if (i >= total) return;
    int row = i >> 5;                                 // 32 uint4 per row
    float f[8];
    if (row < M) {
        const float4* p = (const float4*)(x + ((size_t)i << 3));
        float4 v0 = p[0], v1 = p[1];
        f[0] = v0.x; f[1] = v0.y; f[2] = v0.z; f[3] = v0.w;
        f[4] = v1.x; f[5] = v1.y; f[6] = v1.z; f[7] = v1.w;
    } else {
        #pragma unroll
        for (int j = 0; j < 8; j++) f[j] = 0.f;
    }
    uint32_t hi[4], lo[4];
    #pragma unroll
    for (int j = 0; j < 4; j++) {
        __nv_bfloat16 ha, hb;
        hi[j] = pack_hi2(f[j * 2], f[j * 2 + 1], ha, hb);
        __nv_bfloat16 la = __float2bfloat16_rn(f[j * 2] - __bfloat162float(ha));
        __nv_bfloat16 lb = __float2bfloat16_rn(f[j * 2 + 1] - __bfloat162float(hb));
        lo[j] = ((uint32_t)__bfloat16_as_ushort(lb) << 16) | __bfloat16_as_ushort(la);
    }
    ((uint4*)g_a_hi)[i] = make_uint4(hi[0], hi[1], hi[2], hi[3]);
    ((uint4*)g_a_lo)[i] = make_uint4(lo[0], lo[1], lo[2], lo[3]);
}

// W[k][n] -> WT hi/lo [n][k]
__global__ void k_wt(const float* __restrict__ W) {
    int i = blockIdx.x * blockDim.x + threadIdx.x;   // n*256 + k
    if (i >= DIN * DOUT) return;
    int n = i >> 8, k = i & 255;
    float w = W[k * DOUT + n];
    __nv_bfloat16 hi = __float2bfloat16_rn(w);
    g_wt_hi[i] = hi;
    g_wt_lo[i] = __float2bfloat16_rn(w - __bfloat162float(hi));
}

// ---------------------------------------------------------------------------
// WMMA GEMM: g_h = x @ W via 3-pass bf16 split.
// CTA 128(M) x 128(N), 8 warps as 4(M) x 2(N), warp tile 32x64.
// BK=32 per stage; K=256 -> 8 stages.
// ---------------------------------------------------------------------------
#define LDS 40   // smem leading dim (elements), 80B = 16B multiple
__global__ __launch_bounds__(256) void k_gemm_wmma() {
    __shared__ __align__(16) __nv_bfloat16 sA_hi[128 * LDS];
    __shared__ __align__(16) __nv_bfloat16 sA_lo[128 * LDS];
    __shared__ __align__(16) __nv_bfloat16 sB_hi[128 * LDS];   // BT layout [n][k]
    __shared__ __align__(16) __nv_bfloat16 sB_lo[128 * LDS];

    const int tid = threadIdx.x;
    const int w = tid >> 5;
    const int warp_m = w & 3;          // 0..3
    const int warp_n = w >> 2;         // 0..1
    const int Rbase = blockIdx.x * 128;
    const int Nbase = blockIdx.y * 128;

    wmma::fragment<wmma::accumulator, 16, 16, 16, float> acc[2][4];
    #pragma unroll
    for (int mi = 0; mi < 2; mi++)
        #pragma unroll
        for (int ni = 0; ni < 4; ni++)
            wmma::fill_fragment(acc[mi][ni], 0.0f);

    for (int kc = 0; kc < 8; kc++) {
        // stage: 512 uint4 per array, 2 per thread
        #pragma unroll
        for (int t = 0; t < 2; t++) {
            int idx = tid * 2 + t;         // 0..511
            int r = idx >> 2;              // 0..127
            int seg = idx & 3;             // 8 bf16 per seg
            // A
            {
                const uint4* srch = (const uint4*)g_a_hi +
                    (size_t)(Rbase + r) * 32 + kc * 4 + seg;
                const uint4* srcl = (const uint4*)g_a_lo +
                    (size_t)(Rbase + r) * 32 + kc * 4 + seg;
                *(uint4*)(sA_hi + r * LDS + seg * 8) = *srch;
                *(uint4*)(sA_lo + r * LDS + seg * 8) = *srcl;
            }
            // B (WT rows = n)
            {
                const uint4* srch = (const uint4*)g_wt_hi +
                    (size_t)(Nbase + r) * 32 + kc * 4 + seg;
                const uint4* srcl = (const uint4*)g_wt_lo +
                    (size_t)(Nbase + r) * 32 + kc * 4 + seg;
                *(uint4*)(sB_hi + r * LDS + seg * 8) = *srch;
                *(uint4*)(sB_lo + r * LDS + seg * 8) = *srcl;
            }
        }
        __syncthreads();

        #pragma unroll
        for (int kk = 0; kk < 32; kk += 16) {
            wmma::fragment<wmma::matrix_a, 16, 16, 16, __nv_bfloat16, wmma::row_major> ah[2], al[2];
            #pragma unroll
            for (int mi = 0; mi < 2; mi++) {
                const __nv_bfloat16* pa = sA_hi + (warp_m * 32 + mi * 16) * LDS + kk;
                const __nv_bfloat16* pl = sA_lo + (warp_m * 32 + mi * 16) * LDS + kk;
                wmma::load_matrix_sync(ah[mi], pa, LDS);
                wmma::load_matrix_sync(al[mi], pl, LDS);
            }
            wmma::fragment<wmma::matrix_b, 16, 16, 16, __nv_bfloat16, wmma::col_major> bf[4];
            #pragma unroll
            for (int ni = 0; ni < 4; ni++) {
                const __nv_bfloat16* pb = sB_hi + (warp_n * 64 + ni * 16) * LDS + kk;
                wmma::load_matrix_sync(bf[ni], pb, LDS);
            }
            #pragma unroll
            for (int mi = 0; mi < 2; mi++)
                #pragma unroll
                for (int ni = 0; ni < 4; ni++) {
                    wmma::mma_sync(acc[mi][ni], ah[mi], bf[ni], acc[mi][ni]);
                    wmma::mma_sync(acc[mi][ni], al[mi], bf[ni], acc[mi][ni]);
                }
            #pragma unroll
            for (int ni = 0; ni < 4; ni++) {
                const __nv_bfloat16* pb = sB_lo + (warp_n * 64 + ni * 16) * LDS + kk;
                wmma::load_matrix_sync(bf[ni], pb, LDS);
            }
            #pragma unroll
            for (int mi = 0; mi < 2; mi++)
                #pragma unroll
                for (int ni = 0; ni < 4; ni++)
                    wmma::mma_sync(acc[mi][ni], ah[mi], bf[ni], acc[mi][ni]);
        }
        __syncthreads();
    }

    // epilogue: direct store (rows always < MPAD, padded scratch)
    #pragma unroll
    for (int mi = 0; mi < 2; mi++) {
        int row = Rbase + warp_m * 32 + mi * 16;
        #pragma unroll
        for (int ni = 0; ni < 4; ni++) {
            int col = Nbase + warp_n * 64 + ni * 16;
            wmma::store_matrix_sync(g_h + (size_t)row * DOUT + col,
                                    acc[mi][ni], DOUT, wmma::mem_row_major);
        }
    }
}

// ---------------------------------------------------------------------------
// Node kernel: one warp per destination node
// ---------------------------------------------------------------------------
__global__ __launch_bounds__(256) void k_node(float* __restrict__ out,
                                              const float* __restrict__ b,
                                              const float* __restrict__ gamma,
                                              const float* __restrict__ beta,
                                              const float* __restrict__ mean,
                                              const float* __restrict__ var,
                                              int n) {
    int warp = (blockIdx.x * blockDim.x + threadIdx.x) >> 5;
    int lane = threadIdx.x & 31;
    if (warp >= n) return;

    int node = warp;
    int start = g_off[node];
    int end   = start + g_degi[node];

    float4 acc0 = make_float4(0.f, 0.f, 0.f, 0.f);
    float4 acc1 = make_float4(0.f, 0.f, 0.f, 0.f);

    int e = start;
    for (; e + 1 < end; e += 2) {
        int s0 = g_csr[e];
        int s1 = g_csr[e + 1];
        float w0 = g_dinv[s0];
        float w1 = g_dinv[s1];
        const float4* r0 = (const float4*)(g_h + (size_t)s0 * DOUT);
        const float4* r1 = (const float4*)(g_h + (size_t)s1 * DOUT);
        float4 a0 = r0[lane];
        float4 a1 = r0[lane + 32];
        float4 b0 = r1[lane];
        float4 b1 = r1[lane + 32];
        acc0.x = fmaf(a0.x, w0, acc0.x); acc0.y = fmaf(a0.y, w0, acc0.y);
        acc0.z = fmaf(a0.z, w0, acc0.z); acc0.w = fmaf(a0.w, w0, acc0.w);
        acc1.x = fmaf(a1.x, w0, acc1.x); acc1.y = fmaf(a1.y, w0, acc1.y);
        acc1.z = fmaf(a1.z, w0, acc1.z); acc1.w = fmaf(a1.w, w0, acc1.w);
        acc0.x = fmaf(b0.x, w1, acc0.x); acc0.y = fmaf(b0.y, w1, acc0.y);
        acc0.z = fmaf(b0.z, w1, acc0.z); acc0.w = fmaf(b0.w, w1, acc0.w);
        acc1.x = fmaf(b1.x, w1, acc1.x); acc1.y = fmaf(b1.y, w1, acc1.y);
        acc1.z = fmaf(b1.z, w1, acc1.z); acc1.w = fmaf(b1.w, w1, acc1.w);
    }
    if (e < end) {
        int s0 = g_csr[e];
        float w0 = g_dinv[s0];
        const float4* r0 = (const float4*)(g_h + (size_t)s0 * DOUT);
        float4 a0 = r0[lane];
        float4 a1 = r0[lane + 32];
        acc0.x = fmaf(a0.x, w0, acc0.x); acc0.y = fmaf(a0.y, w0, acc0.y);
        acc0.z = fmaf(a0.z, w0, acc0.z); acc0.w = fmaf(a0.w, w0, acc0.w);
        acc1.x = fmaf(a1.x, w0, acc1.x); acc1.y = fmaf(a1.y, w0, acc1.y);
        acc1.z = fmaf(a1.z, w0, acc1.z); acc1.w = fmaf(a1.w, w0, acc1.w);
    }

    float di = g_dinv[node];
    const float4* hr = (const float4*)(g_h + (size_t)node * DOUT);
    float4 h0 = hr[lane];
    float4 h1 = hr[lane + 32];
    acc0.x = fmaf(h0.x, di, acc0.x); acc0.y = fmaf(h0.y, di, acc0.y);
    acc0.z = fmaf(h0.z, di, acc0.z); acc0.w = fmaf(h0.w, di, acc0.w);
    acc1.x = fmaf(h1.x, di, acc1.x); acc1.y = fmaf(h1.y, di, acc1.y);
    acc1.z = fmaf(h1.z, di, acc1.z); acc1.w = fmaf(h1.w, di, acc1.w);
    acc0.x *= di; acc0.y *= di; acc0.z *= di; acc0.w *= di;
    acc1.x *= di; acc1.y *= di; acc1.z *= di; acc1.w *= di;

    #pragma unroll
    for (int half = 0; half < 2; half++) {
        int c4 = lane + half * 32;
        float4 bv = ((const float4*)b)[c4];
        float4 gv = ((const float4*)gamma)[c4];
        float4 tv = ((const float4*)beta)[c4];
        float4 mv = ((const float4*)mean)[c4];
        float4 vv = ((const float4*)var)[c4];
        float4 a = half ? acc1 : acc0;
        float4 r;
        float sx = gv.x * rsqrtf(vv.x + 1e-5f);
        float sy = gv.y * rsqrtf(vv.y + 1e-5f);
        float sz = gv.z * rsqrtf(vv.z + 1e-5f);
        float sw = gv.w * rsqrtf(vv.w + 1e-5f);
        r.x = fmaxf(fmaf(a.x + bv.x - mv.x, sx, tv.x), 0.f);
        r.y = fmaxf(fmaf(a.y + bv.y - mv.y, sy, tv.y), 0.f);
        r.z = fmaxf(fmaf(a.z + bv.z - mv.z, sz, tv.z), 0.f);
        r.w = fmaxf(fmaf(a.w + bv.w - mv.w, sw, tv.w), 0.f);
        ((float4*)(out + (size_t)node * DOUT))[c4] = r;
    }
}

// ---------------------------------------------------------------------------
extern "C" void kernel_launch(void* const* d_in, const int* in_sizes, int n_in,
                              void* d_out, int out_size) {
    const float* x      = (const float*)d_in[0];
    const int*   ei     = (const int*)d_in[1];   // int32 (jax x64 disabled)
    const float* W      = (const float*)d_in[2];
    const float* b      = (const float*)d_in[3];
    const float* gamma  = (const float*)d_in[4];
    const float* beta   = (const float*)d_in[5];
    const float* rmean  = (const float*)d_in[6];
    const float* rvar   = (const float*)d_in[7];
    float* out = (float*)d_out;

    int N = in_sizes[0] / DIN;     // 50000
    int E = in_sizes[1] / 2;       // 800000
    const int* src = ei;
    const int* dst = ei + E;
    int nb = (N + 1023) / 1024;

    k_zero<<<(N + 255) / 256, 256>>>(N);
    k_count<<<(E + 255) / 256, 256>>>(dst, E);
    k_scan1<<<nb, 1024>>>(N);
    k_scan2<<<1, 64>>>(nb);
    k_scan3<<<nb, 1024>>>(N);
    k_fill<<<(E + 255) / 256, 256>>>(src, dst, E);

    k_wt<<<(DIN * DOUT + 255) / 256, 256>>>(W);
    int splitn = MPAD * DIN / 8;
    k_split<<<(splitn + 255) / 256, 256>>>(x, N);

    dim3 ggrid(MPAD / 128, DOUT / 128);
    k_gemm_wmma<<<ggrid, 256>>>();

    long long nthreads = (long long)N * 32;
    k_node<<<(int)((nthreads + 255) / 256), 256>>>(out, b, gamma, beta,
                                                   rmean, rvar, N);
}

// round 6
// speedup vs baseline: 1.4209x; 1.0419x over previous
#include <cuda_runtime.h>
#include <cuda_bf16.h>
#include <cuda_pipeline.h>
#include <mma.h>
#include <cstdint>

using namespace nvcuda;

#define NNODES 50000
#define MPAD   50048          // 391 * 128
#define EMAX   800000
#define DOUT   256
#define DIN    256

// ---------------------------------------------------------------------------
// Scratch (device globals)
// ---------------------------------------------------------------------------
__device__ float g_h[(size_t)MPAD * DOUT];       // x @ W (fp32, padded rows)
__device__ int   g_degi[NNODES];
__device__ int   g_off[NNODES];
__device__ int   g_cur[NNODES];
__device__ float g_dinv[NNODES];
__device__ int   g_csr[EMAX];
__device__ int   g_bsum[64];
__device__ __nv_bfloat16 g_a_hi[(size_t)MPAD * DIN];
__device__ __nv_bfloat16 g_a_lo[(size_t)MPAD * DIN];
__device__ __nv_bfloat16 g_wt_hi[DOUT * DIN];    // W^T [n][k], k contiguous
__device__ __nv_bfloat16 g_wt_lo[DOUT * DIN];

// ---------------------------------------------------------------------------
// Degree / CSR build
// ---------------------------------------------------------------------------
__global__ void k_zero(int n) {
    int i = blockIdx.x * blockDim.x + threadIdx.x;
    if (i < n) g_degi[i] = 0;
}
__global__ void k_count(const int* __restrict__ dst, int E) {
    int i = blockIdx.x * blockDim.x + threadIdx.x;
    if (i < E) atomicAdd(&g_degi[dst[i]], 1);
}

__global__ __launch_bounds__(1024) void k_scan1(int n) {
    __shared__ int wsum[32];
    int tid = threadIdx.x, lane = tid & 31, wid = tid >> 5;
    int i = blockIdx.x * 1024 + tid;
    int v = (i < n) ? g_degi[i] : 0;
    if (i < n) g_dinv[i] = rsqrtf((float)(v + 1));
    int sc = v;
    #pragma unroll
    for (int o = 1; o < 32; o <<= 1) {
        int t = __shfl_up_sync(0xffffffffu, sc, o);
        if (lane >= o) sc += t;
    }
    if (lane == 31) wsum[wid] = sc;
    __syncthreads();
    if (wid == 0) {
        int s = wsum[lane];
        #pragma unroll
        for (int o = 1; o < 32; o <<= 1) {
            int t = __shfl_up_sync(0xffffffffu, s, o);
            if (lane >= o) s += t;
        }
        wsum[lane] = s;
    }
    __syncthreads();
    int warpoff = (wid > 0) ? wsum[wid - 1] : 0;
    if (i < n) g_off[i] = warpoff + sc - v;
    if (tid == 0) g_bsum[blockIdx.x] = wsum[31];
}

__global__ void k_scan2(int nb) {
    __shared__ int w0tot;
    int t = threadIdx.x, lane = t & 31, wid = t >> 5;
    int v = (t < nb) ? g_bsum[t] : 0;
    int sc = v;
    #pragma unroll
    for (int o = 1; o < 32; o <<= 1) {
        int x = __shfl_up_sync(0xffffffffu, sc, o);
        if (lane >= o) sc += x;
    }
    if (wid == 0 && lane == 31) w0tot = sc;
    __syncthreads();
    int excl = sc - v + (wid ? w0tot : 0);
    if (t < nb) g_bsum[t] = excl;
}

__global__ __launch_bounds__(1024) void k_scan3(int n) {
    int i = blockIdx.x * 1024 + threadIdx.x;
    if (i >= n) return;
    int o = g_off[i] + g_bsum[blockIdx.x];
    g_off[i] = o;
    g_cur[i] = o;
}

__global__ void k_fill(const int* __restrict__ src,
                       const int* __restrict__ dst, int E) {
    int i = blockIdx.x * blockDim.x + threadIdx.x;
    if (i >= E) return;
    int d = dst[i];
    int pos = atomicAdd(&g_cur[d], 1);
    g_csr[pos] = src[i];
}

// ---------------------------------------------------------------------------
// Split prep
// ---------------------------------------------------------------------------
__global__ void k_split(const float* __restrict__ x, int M) {
    int i = blockIdx.x * blockDim.x + threadIdx.x;   // uint4 index (8 bf16)
    int total = MPAD * DIN / 8;
    if (i >= total) return;
    int row = i >> 5;                                 // 32 uint4 per row
    float f[8];
    if (row < M) {
        const float4* p = (const float4*)(x + ((size_t)i << 3));
        float4 v0 = p[0], v1 = p[1];
        f[0] = v0.x; f[1] = v0.y; f[2] = v0.z; f[3] = v0.w;
        f[4] = v1.x; f[5] = v1.y; f[6] = v1.z; f[7] = v1.w;
    } else {
        #pragma unroll
        for (int j = 0; j < 8; j++) f[j] = 0.f;
    }
    uint32_t hi[4], lo[4];
    #pragma unroll
    for (int j = 0; j < 4; j++) {
        __nv_bfloat16 ha = __float2bfloat16_rn(f[j * 2]);
        __nv_bfloat16 hb = __float2bfloat16_rn(f[j * 2 + 1]);
        hi[j] = ((uint32_t)__bfloat16_as_ushort(hb) << 16) | __bfloat16_as_ushort(ha);
        __nv_bfloat16 la = __float2bfloat16_rn(f[j * 2] - __bfloat162float(ha));
        __nv_bfloat16 lb = __float2bfloat16_rn(f[j * 2 + 1] - __bfloat162float(hb));
        lo[j] = ((uint32_t)__bfloat16_as_ushort(lb) << 16) | __bfloat16_as_ushort(la);
    }
    ((uint4*)g_a_hi)[i] = make_uint4(hi[0], hi[1], hi[2], hi[3]);
    ((uint4*)g_a_lo)[i] = make_uint4(lo[0], lo[1], lo[2], lo[3]);
}

__global__ void k_wt(const float* __restrict__ W) {
    int i = blockIdx.x * blockDim.x + threadIdx.x;   // n*256 + k
    if (i >= DIN * DOUT) return;
    int n = i >> 8, k = i & 255;
    float w = W[k * DOUT + n];
    __nv_bfloat16 hi = __float2bfloat16_rn(w);
    g_wt_hi[i] = hi;
    g_wt_lo[i] = __float2bfloat16_rn(w - __bfloat162float(hi));
}

// ---------------------------------------------------------------------------
// WMMA GEMM: g_h = x @ W via 3-pass bf16 split.
// CTA 128(M) x 128(N), 8 warps as 4(M) x 2(N), warp tile 32x64.
// BK=32 per stage; K=256 -> 8 stages. cp.async staging.
// ---------------------------------------------------------------------------
#define LDS 40
__global__ __launch_bounds__(256) void k_gemm_wmma() {
    __shared__ __align__(16) __nv_bfloat16 sA_hi[128 * LDS];
    __shared__ __align__(16) __nv_bfloat16 sA_lo[128 * LDS];
    __shared__ __align__(16) __nv_bfloat16 sB_hi[128 * LDS];
    __shared__ __align__(16) __nv_bfloat16 sB_lo[128 * LDS];

    const int tid = threadIdx.x;
    const int w = tid >> 5;
    const int warp_m = w & 3;
    const int warp_n = w >> 2;
    const int Rbase = blockIdx.x * 128;
    const int Nbase = blockIdx.y * 128;

    wmma::fragment<wmma::accumulator, 16, 16, 16, float> acc[2][4];
    #pragma unroll
    for (int mi = 0; mi < 2; mi++)
        #pragma unroll
        for (int ni = 0; ni < 4; ni++)
            wmma::fill_fragment(acc[mi][ni], 0.0f);

    for (int kc = 0; kc < 8; kc++) {
        #pragma unroll
        for (int t = 0; t < 2; t++) {
            int idx = tid * 2 + t;         // 0..511
            int r = idx >> 2;              // 0..127
            int seg = idx & 3;
            __pipeline_memcpy_async(sA_hi + r * LDS + seg * 8,
                (const uint4*)g_a_hi + (size_t)(Rbase + r) * 32 + kc * 4 + seg, 16);
            __pipeline_memcpy_async(sA_lo + r * LDS + seg * 8,
                (const uint4*)g_a_lo + (size_t)(Rbase + r) * 32 + kc * 4 + seg, 16);
            __pipeline_memcpy_async(sB_hi + r * LDS + seg * 8,
                (const uint4*)g_wt_hi + (size_t)(Nbase + r) * 32 + kc * 4 + seg, 16);
            __pipeline_memcpy_async(sB_lo + r * LDS + seg * 8,
                (const uint4*)g_wt_lo + (size_t)(Nbase + r) * 32 + kc * 4 + seg, 16);
        }
        __pipeline_commit();
        __pipeline_wait_prior(0);
        __syncthreads();

        #pragma unroll
        for (int kk = 0; kk < 32; kk += 16) {
            wmma::fragment<wmma::matrix_a, 16, 16, 16, __nv_bfloat16, wmma::row_major> ah[2], al[2];
            #pragma unroll
            for (int mi = 0; mi < 2; mi++) {
                wmma::load_matrix_sync(ah[mi], sA_hi + (warp_m * 32 + mi * 16) * LDS + kk, LDS);
                wmma::load_matrix_sync(al[mi], sA_lo + (warp_m * 32 + mi * 16) * LDS + kk, LDS);
            }
            wmma::fragment<wmma::matrix_b, 16, 16, 16, __nv_bfloat16, wmma::col_major> bf[4];
            #pragma unroll
            for (int ni = 0; ni < 4; ni++)
                wmma::load_matrix_sync(bf[ni], sB_hi + (warp_n * 64 + ni * 16) * LDS + kk, LDS);
            #pragma unroll
            for (int mi = 0; mi < 2; mi++)
                #pragma unroll
                for (int ni = 0; ni < 4; ni++) {
                    wmma::mma_sync(acc[mi][ni], ah[mi], bf[ni], acc[mi][ni]);
                    wmma::mma_sync(acc[mi][ni], al[mi], bf[ni], acc[mi][ni]);
                }
            #pragma unroll
            for (int ni = 0; ni < 4; ni++)
                wmma::load_matrix_sync(bf[ni], sB_lo + (warp_n * 64 + ni * 16) * LDS + kk, LDS);
            #pragma unroll
            for (int mi = 0; mi < 2; mi++)
                #pragma unroll
                for (int ni = 0; ni < 4; ni++)
                    wmma::mma_sync(acc[mi][ni], ah[mi], bf[ni], acc[mi][ni]);
        }
        __syncthreads();
    }

    #pragma unroll
    for (int mi = 0; mi < 2; mi++) {
        int row = Rbase + warp_m * 32 + mi * 16;
        #pragma unroll
        for (int ni = 0; ni < 4; ni++) {
            int col = Nbase + warp_n * 64 + ni * 16;
            wmma::store_matrix_sync(g_h + (size_t)row * DOUT + col,
                                    acc[mi][ni], DOUT, wmma::mem_row_major);
        }
    }
}

// ---------------------------------------------------------------------------
// Node kernel: one warp per destination node, 4-edge unroll (MLP=8)
// ---------------------------------------------------------------------------
#define FMA4(acc, v, s) \
    acc.x = fmaf((v).x, (s), acc.x); acc.y = fmaf((v).y, (s), acc.y); \
    acc.z = fmaf((v).z, (s), acc.z); acc.w = fmaf((v).w, (s), acc.w)

__global__ __launch_bounds__(256) void k_node(float* __restrict__ out,
                                              const float* __restrict__ b,
                                              const float* __restrict__ gamma,
                                              const float* __restrict__ beta,
                                              const float* __restrict__ mean,
                                              const float* __restrict__ var,
                                              int n) {
    int warp = (blockIdx.x * blockDim.x + threadIdx.x) >> 5;
    int lane = threadIdx.x & 31;
    if (warp >= n) return;

    int node = warp;
    int start = g_off[node];
    int end   = start + g_degi[node];

    float4 acc0 = make_float4(0.f, 0.f, 0.f, 0.f);
    float4 acc1 = make_float4(0.f, 0.f, 0.f, 0.f);

    int e = start;
    for (; e + 3 < end; e += 4) {
        int s0 = g_csr[e + 0], s1 = g_csr[e + 1];
        int s2 = g_csr[e + 2], s3 = g_csr[e + 3];
        float w0 = g_dinv[s0], w1 = g_dinv[s1];
        float w2 = g_dinv[s2], w3 = g_dinv[s3];
        const float4* r0 = (const float4*)(g_h + (size_t)s0 * DOUT);
        const float4* r1 = (const float4*)(g_h + (size_t)s1 * DOUT);
        const float4* r2 = (const float4*)(g_h + (size_t)s2 * DOUT);
        const float4* r3 = (const float4*)(g_h + (size_t)s3 * DOUT);
        float4 a0 = __ldg(r0 + lane),      a1 = __ldg(r0 + lane + 32);
        float4 b0 = __ldg(r1 + lane),      b1 = __ldg(r1 + lane + 32);
        float4 c0 = __ldg(r2 + lane),      c1 = __ldg(r2 + lane + 32);
        float4 d0 = __ldg(r3 + lane),      d1 = __ldg(r3 + lane + 32);
        FMA4(acc0, a0, w0); FMA4(acc1, a1, w0);
        FMA4(acc0, b0, w1); FMA4(acc1, b1, w1);
        FMA4(acc0, c0, w2); FMA4(acc1, c1, w2);
        FMA4(acc0, d0, w3); FMA4(acc1, d1, w3);
    }
    for (; e < end; e++) {
        int s0 = g_csr[e];
        float w0 = g_dinv[s0];
        const float4* r0 = (const float4*)(g_h + (size_t)s0 * DOUT);
        float4 a0 = __ldg(r0 + lane), a1 = __ldg(r0 + lane + 32);
        FMA4(acc0, a0, w0); FMA4(acc1, a1, w0);
    }

    float di = g_dinv[node];
    const float4* hr = (const float4*)(g_h + (size_t)node * DOUT);
    float4 h0 = __ldg(hr + lane), h1 = __ldg(hr + lane + 32);
    FMA4(acc0, h0, di); FMA4(acc1, h1, di);
    acc0.x *= di; acc0.y *= di; acc0.z *= di; acc0.w *= di;
    acc1.x *= di; acc1.y *= di; acc1.z *= di; acc1.w *= di;

    #pragma unroll
    for (int half = 0; half < 2; half++) {
        int c4 = lane + half * 32;
        float4 bv = ((const float4*)b)[c4];
        float4 gv = ((const float4*)gamma)[c4];
        float4 tv = ((const float4*)beta)[c4];
        float4 mv = ((const float4*)mean)[c4];
        float4 vv = ((const float4*)var)[c4];
        float4 a = half ? acc1 : acc0;
        float4 r;
        float sx = gv.x * rsqrtf(vv.x + 1e-5f);
        float sy = gv.y * rsqrtf(vv.y + 1e-5f);
        float sz = gv.z * rsqrtf(vv.z + 1e-5f);
        float sw = gv.w * rsqrtf(vv.w + 1e-5f);
        r.x = fmaxf(fmaf(a.x + bv.x - mv.x, sx, tv.x), 0.f);
        r.y = fmaxf(fmaf(a.y + bv.y - mv.y, sy, tv.y), 0.f);
        r.z = fmaxf(fmaf(a.z + bv.z - mv.z, sz, tv.z), 0.f);
        r.w = fmaxf(fmaf(a.w + bv.w - mv.w, sw, tv.w), 0.f);
        ((float4*)(out + (size_t)node * DOUT))[c4] = r;
    }
}

// ---------------------------------------------------------------------------
// Launch order puts k_gemm_wmma at profile slot #4 (ncu -s5 -c1 lands there).
// Dependencies: gemm needs wt+split; count needs zero; node needs all.
// ---------------------------------------------------------------------------
extern "C" void kernel_launch(void* const* d_in, const int* in_sizes, int n_in,
                              void* d_out, int out_size) {
    const float* x      = (const float*)d_in[0];
    const int*   ei     = (const int*)d_in[1];   // int32 (jax x64 disabled)
    const float* W      = (const float*)d_in[2];
    const float* b      = (const float*)d_in[3];
    const float* gamma  = (const float*)d_in[4];
    const float* beta   = (const float*)d_in[5];
    const float* rmean  = (const float*)d_in[6];
    const float* rvar   = (const float*)d_in[7];
    float* out = (float*)d_out;

    int N = in_sizes[0] / DIN;     // 50000
    int E = in_sizes[1] / 2;       // 800000
    const int* src = ei;
    const int* dst = ei + E;
    int nb = (N + 1023) / 1024;

    // 1-3: GEMM prerequisites + degi zero
    k_wt<<<(DIN * DOUT + 255) / 256, 256>>>(W);
    int splitn = MPAD * DIN / 8;
    k_split<<<(splitn + 255) / 256, 256>>>(x, N);
    k_zero<<<(N + 255) / 256, 256>>>(N);

    // 4: GEMM (profiled slot)
    dim3 ggrid(MPAD / 128, DOUT / 128);
    k_gemm_wmma<<<ggrid, 256>>>();

    // 5-9: CSR build
    k_count<<<(E + 255) / 256, 256>>>(dst, E);
    k_scan1<<<nb, 1024>>>(N);
    k_scan2<<<1, 64>>>(nb);
    k_scan3<<<nb, 1024>>>(N);
    k_fill<<<(E + 255) / 256, 256>>>(src, dst, E);

    // 10: gather + epilogue
    long long nthreads = (long long)N * 32;
    k_node<<<(int)((nthreads + 255) / 256), 256>>>(out, b, gamma, beta,
                                                   rmean, rvar, N);
}

// round 7
// speedup vs baseline: 1.5785x; 1.1109x over previous
#include <cuda_runtime.h>
#include <cuda_bf16.h>
#include <cuda_pipeline.h>
#include <mma.h>
#include <cstdint>

using namespace nvcuda;

#define NNODES 50000
#define MPAD   50048          // 391 * 128
#define EMAX   800000
#define DOUT   256
#define DIN    256

// ---------------------------------------------------------------------------
// Scratch (device globals)
// ---------------------------------------------------------------------------
__device__ float g_h[(size_t)MPAD * DOUT];       // x @ W (fp32, padded rows)
__device__ int   g_degi[NNODES];
__device__ int   g_off[NNODES];
__device__ int   g_cur[NNODES];
__device__ float g_dinv[NNODES];
__device__ int   g_csr[EMAX];
__device__ int   g_bsum[64];
__device__ __nv_bfloat16 g_a_hi[(size_t)MPAD * DIN];
__device__ __nv_bfloat16 g_a_lo[(size_t)MPAD * DIN];
__device__ __nv_bfloat16 g_wt_hi[DOUT * DIN];    // W^T [n][k], k contiguous
__device__ __nv_bfloat16 g_wt_lo[DOUT * DIN];

// ---------------------------------------------------------------------------
// Degree / CSR build
// ---------------------------------------------------------------------------
__global__ void k_zero(int n) {
    int i = blockIdx.x * blockDim.x + threadIdx.x;
    if (i < n) g_degi[i] = 0;
}
__global__ void k_count(const int* __restrict__ dst, int E) {
    int i = blockIdx.x * blockDim.x + threadIdx.x;
    if (i < E) atomicAdd(&g_degi[dst[i]], 1);
}

__global__ __launch_bounds__(1024) void k_scan1(int n) {
    __shared__ int wsum[32];
    int tid = threadIdx.x, lane = tid & 31, wid = tid >> 5;
    int i = blockIdx.x * 1024 + tid;
    int v = (i < n) ? g_degi[i] : 0;
    if (i < n) g_dinv[i] = rsqrtf((float)(v + 1));
    int sc = v;
    #pragma unroll
    for (int o = 1; o < 32; o <<= 1) {
        int t = __shfl_up_sync(0xffffffffu, sc, o);
        if (lane >= o) sc += t;
    }
    if (lane == 31) wsum[wid] = sc;
    __syncthreads();
    if (wid == 0) {
        int s = wsum[lane];
        #pragma unroll
        for (int o = 1; o < 32; o <<= 1) {
            int t = __shfl_up_sync(0xffffffffu, s, o);
            if (lane >= o) s += t;
        }
        wsum[lane] = s;
    }
    __syncthreads();
    int warpoff = (wid > 0) ? wsum[wid - 1] : 0;
    if (i < n) g_off[i] = warpoff + sc - v;
    if (tid == 0) g_bsum[blockIdx.x] = wsum[31];
}

__global__ void k_scan2(int nb) {
    __shared__ int w0tot;
    int t = threadIdx.x, lane = t & 31, wid = t >> 5;
    int v = (t < nb) ? g_bsum[t] : 0;
    int sc = v;
    #pragma unroll
    for (int o = 1; o < 32; o <<= 1) {
        int x = __shfl_up_sync(0xffffffffu, sc, o);
        if (lane >= o) sc += x;
    }
    if (wid == 0 && lane == 31) w0tot = sc;
    __syncthreads();
    int excl = sc - v + (wid ? w0tot : 0);
    if (t < nb) g_bsum[t] = excl;
}

__global__ __launch_bounds__(1024) void k_scan3(int n) {
    int i = blockIdx.x * 1024 + threadIdx.x;
    if (i >= n) return;
    int o = g_off[i] + g_bsum[blockIdx.x];
    g_off[i] = o;
    g_cur[i] = o;
}

__global__ void k_fill(const int* __restrict__ src,
                       const int* __restrict__ dst, int E) {
    int i = blockIdx.x * blockDim.x + threadIdx.x;
    if (i >= E) return;
    int d = dst[i];
    int pos = atomicAdd(&g_cur[d], 1);
    g_csr[pos] = src[i];
}

// ---------------------------------------------------------------------------
// Split prep
// ---------------------------------------------------------------------------
__global__ void k_split(const float* __restrict__ x, int M) {
    int i = blockIdx.x * blockDim.x + threadIdx.x;   // uint4 index (8 bf16)
    int total = MPAD * DIN / 8;
    if (i >= total) return;
    int row = i >> 5;                                 // 32 uint4 per row
    float f[8];
    if (row < M) {
        const float4* p = (const float4*)(x + ((size_t)i << 3));
        float4 v0 = p[0], v1 = p[1];
        f[0] = v0.x; f[1] = v0.y; f[2] = v0.z; f[3] = v0.w;
        f[4] = v1.x; f[5] = v1.y; f[6] = v1.z; f[7] = v1.w;
    } else {
        #pragma unroll
        for (int j = 0; j < 8; j++) f[j] = 0.f;
    }
    uint32_t hi[4], lo[4];
    #pragma unroll
    for (int j = 0; j < 4; j++) {
        __nv_bfloat16 ha = __float2bfloat16_rn(f[j * 2]);
        __nv_bfloat16 hb = __float2bfloat16_rn(f[j * 2 + 1]);
        hi[j] = ((uint32_t)__bfloat16_as_ushort(hb) << 16) | __bfloat16_as_ushort(ha);
        __nv_bfloat16 la = __float2bfloat16_rn(f[j * 2] - __bfloat162float(ha));
        __nv_bfloat16 lb = __float2bfloat16_rn(f[j * 2 + 1] - __bfloat162float(hb));
        lo[j] = ((uint32_t)__bfloat16_as_ushort(lb) << 16) | __bfloat16_as_ushort(la);
    }
    ((uint4*)g_a_hi)[i] = make_uint4(hi[0], hi[1], hi[2], hi[3]);
    ((uint4*)g_a_lo)[i] = make_uint4(lo[0], lo[1], lo[2], lo[3]);
}

__global__ void k_wt(const float* __restrict__ W) {
    int i = blockIdx.x * blockDim.x + threadIdx.x;   // n*256 + k
    if (i >= DIN * DOUT) return;
    int n = i >> 8, k = i & 255;
    float w = W[k * DOUT + n];
    __nv_bfloat16 hi = __float2bfloat16_rn(w);
    g_wt_hi[i] = hi;
    g_wt_lo[i] = __float2bfloat16_rn(w - __bfloat162float(hi));
}

// ---------------------------------------------------------------------------
// WMMA GEMM, double-buffered cp.async mainloop.
// CTA 128(M) x 128(N), 8 warps 4x2, warp tile 32x64. BK=32, 8 chunks.
// Dynamic smem: 2 stages x 4 arrays x 128 x LDS bf16 = 80 KB.
// ---------------------------------------------------------------------------
#define LDS 40
#define STAGE_ELEMS (128 * LDS)          // per array
#define STAGE_TOTAL (4 * STAGE_ELEMS)    // per stage (4 arrays)

__global__ __launch_bounds__(256) void k_gemm_wmma() {
    extern __shared__ __align__(16) __nv_bfloat16 smd[];

    const int tid = threadIdx.x;
    const int w = tid >> 5;
    const int warp_m = w & 3;
    const int warp_n = w >> 2;
    const int Rbase = blockIdx.x * 128;
    const int Nbase = blockIdx.y * 128;

    // staging indices for this thread (2 chunks of 16B per array)
    const int idx0 = tid * 2;
    const int r0 = idx0 >> 2, seg0 = idx0 & 3;
    const int r1 = (idx0 + 1) >> 2, seg1 = (idx0 + 1) & 3;

    auto prefetch = [&](int kc, int stage) {
        __nv_bfloat16* base = smd + stage * STAGE_TOTAL;
        __nv_bfloat16* dA_hi = base;
        __nv_bfloat16* dA_lo = base + STAGE_ELEMS;
        __nv_bfloat16* dB_hi = base + 2 * STAGE_ELEMS;
        __nv_bfloat16* dB_lo = base + 3 * STAGE_ELEMS;
        __pipeline_memcpy_async(dA_hi + r0 * LDS + seg0 * 8,
            (const uint4*)g_a_hi + (size_t)(Rbase + r0) * 32 + kc * 4 + seg0, 16);
        __pipeline_memcpy_async(dA_hi + r1 * LDS + seg1 * 8,
            (const uint4*)g_a_hi + (size_t)(Rbase + r1) * 32 + kc * 4 + seg1, 16);
        __pipeline_memcpy_async(dA_lo + r0 * LDS + seg0 * 8,
            (const uint4*)g_a_lo + (size_t)(Rbase + r0) * 32 + kc * 4 + seg0, 16);
        __pipeline_memcpy_async(dA_lo + r1 * LDS + seg1 * 8,
            (const uint4*)g_a_lo + (size_t)(Rbase + r1) * 32 + kc * 4 + seg1, 16);
        __pipeline_memcpy_async(dB_hi + r0 * LDS + seg0 * 8,
            (const uint4*)g_wt_hi + (size_t)(Nbase + r0) * 32 + kc * 4 + seg0, 16);
        __pipeline_memcpy_async(dB_hi + r1 * LDS + seg1 * 8,
            (const uint4*)g_wt_hi + (size_t)(Nbase + r1) * 32 + kc * 4 + seg1, 16);
        __pipeline_memcpy_async(dB_lo + r0 * LDS + seg0 * 8,
            (const uint4*)g_wt_lo + (size_t)(Nbase + r0) * 32 + kc * 4 + seg0, 16);
        __pipeline_memcpy_async(dB_lo + r1 * LDS + seg1 * 8,
            (const uint4*)g_wt_lo + (size_t)(Nbase + r1) * 32 + kc * 4 + seg1, 16);
        __pipeline_commit();
    };

    wmma::fragment<wmma::accumulator, 16, 16, 16, float> acc[2][4];
    #pragma unroll
    for (int mi = 0; mi < 2; mi++)
        #pragma unroll
        for (int ni = 0; ni < 4; ni++)
            wmma::fill_fragment(acc[mi][ni], 0.0f);

    prefetch(0, 0);

    for (int kc = 0; kc < 8; kc++) {
        if (kc < 7) prefetch(kc + 1, (kc + 1) & 1);
        __pipeline_wait_prior(kc < 7 ? 1 : 0);
        __syncthreads();

        __nv_bfloat16* base = smd + (kc & 1) * STAGE_TOTAL;
        __nv_bfloat16* sA_hi = base;
        __nv_bfloat16* sA_lo = base + STAGE_ELEMS;
        __nv_bfloat16* sB_hi = base + 2 * STAGE_ELEMS;
        __nv_bfloat16* sB_lo = base + 3 * STAGE_ELEMS;

        #pragma unroll
        for (int kk = 0; kk < 32; kk += 16) {
            wmma::fragment<wmma::matrix_a, 16, 16, 16, __nv_bfloat16, wmma::row_major> ah[2], al[2];
            #pragma unroll
            for (int mi = 0; mi < 2; mi++) {
                wmma::load_matrix_sync(ah[mi], sA_hi + (warp_m * 32 + mi * 16) * LDS + kk, LDS);
                wmma::load_matrix_sync(al[mi], sA_lo + (warp_m * 32 + mi * 16) * LDS + kk, LDS);
            }
            wmma::fragment<wmma::matrix_b, 16, 16, 16, __nv_bfloat16, wmma::col_major> bf[4];
            #pragma unroll
            for (int ni = 0; ni < 4; ni++)
                wmma::load_matrix_sync(bf[ni], sB_hi + (warp_n * 64 + ni * 16) * LDS + kk, LDS);
            #pragma unroll
            for (int mi = 0; mi < 2; mi++)
                #pragma unroll
                for (int ni = 0; ni < 4; ni++) {
                    wmma::mma_sync(acc[mi][ni], ah[mi], bf[ni], acc[mi][ni]);
                    wmma::mma_sync(acc[mi][ni], al[mi], bf[ni], acc[mi][ni]);
                }
            #pragma unroll
            for (int ni = 0; ni < 4; ni++)
                wmma::load_matrix_sync(bf[ni], sB_lo + (warp_n * 64 + ni * 16) * LDS + kk, LDS);
            #pragma unroll
            for (int mi = 0; mi < 2; mi++)
                #pragma unroll
                for (int ni = 0; ni < 4; ni++)
                    wmma::mma_sync(acc[mi][ni], ah[mi], bf[ni], acc[mi][ni]);
        }
        __syncthreads();
    }

    #pragma unroll
    for (int mi = 0; mi < 2; mi++) {
        int row = Rbase + warp_m * 32 + mi * 16;
        #pragma unroll
        for (int ni = 0; ni < 4; ni++) {
            int col = Nbase + warp_n * 64 + ni * 16;
            wmma::store_matrix_sync(g_h + (size_t)row * DOUT + col,
                                    acc[mi][ni], DOUT, wmma::mem_row_major);
        }
    }
}

// ---------------------------------------------------------------------------
// Node kernel: one warp per destination node, 4-edge unroll
// ---------------------------------------------------------------------------
#define FMA4(acc, v, s) \
    acc.x = fmaf((v).x, (s), acc.x); acc.y = fmaf((v).y, (s), acc.y); \
    acc.z = fmaf((v).z, (s), acc.z); acc.w = fmaf((v).w, (s), acc.w)

__global__ __launch_bounds__(256) void k_node(float* __restrict__ out,
                                              const float* __restrict__ b,
                                              const float* __restrict__ gamma,
                                              const float* __restrict__ beta,
                                              const float* __restrict__ mean,
                                              const float* __restrict__ var,
                                              int n) {
    int warp = (blockIdx.x * blockDim.x + threadIdx.x) >> 5;
    int lane = threadIdx.x & 31;
    if (warp >= n) return;

    int node = warp;
    int start = g_off[node];
    int end   = start + g_degi[node];

    float4 acc0 = make_float4(0.f, 0.f, 0.f, 0.f);
    float4 acc1 = make_float4(0.f, 0.f, 0.f, 0.f);

    int e = start;
    for (; e + 3 < end; e += 4) {
        int s0 = g_csr[e + 0], s1 = g_csr[e + 1];
        int s2 = g_csr[e + 2], s3 = g_csr[e + 3];
        float w0 = g_dinv[s0], w1 = g_dinv[s1];
        float w2 = g_dinv[s2], w3 = g_dinv[s3];
        const float4* r0 = (const float4*)(g_h + (size_t)s0 * DOUT);
        const float4* r1 = (const float4*)(g_h + (size_t)s1 * DOUT);
        const float4* r2 = (const float4*)(g_h + (size_t)s2 * DOUT);
        const float4* r3 = (const float4*)(g_h + (size_t)s3 * DOUT);
        float4 a0 = __ldg(r0 + lane),      a1 = __ldg(r0 + lane + 32);
        float4 b0 = __ldg(r1 + lane),      b1 = __ldg(r1 + lane + 32);
        float4 c0 = __ldg(r2 + lane),      c1 = __ldg(r2 + lane + 32);
        float4 d0 = __ldg(r3 + lane),      d1 = __ldg(r3 + lane + 32);
        FMA4(acc0, a0, w0); FMA4(acc1, a1, w0);
        FMA4(acc0, b0, w1); FMA4(acc1, b1, w1);
        FMA4(acc0, c0, w2); FMA4(acc1, c1, w2);
        FMA4(acc0, d0, w3); FMA4(acc1, d1, w3);
    }
    for (; e < end; e++) {
        int s0 = g_csr[e];
        float w0 = g_dinv[s0];
        const float4* r0 = (const float4*)(g_h + (size_t)s0 * DOUT);
        float4 a0 = __ldg(r0 + lane), a1 = __ldg(r0 + lane + 32);
        FMA4(acc0, a0, w0); FMA4(acc1, a1, w0);
    }

    float di = g_dinv[node];
    const float4* hr = (const float4*)(g_h + (size_t)node * DOUT);
    float4 h0 = __ldg(hr + lane), h1 = __ldg(hr + lane + 32);
    FMA4(acc0, h0, di); FMA4(acc1, h1, di);
    acc0.x *= di; acc0.y *= di; acc0.z *= di; acc0.w *= di;
    acc1.x *= di; acc1.y *= di; acc1.z *= di; acc1.w *= di;

    #pragma unroll
    for (int half = 0; half < 2; half++) {
        int c4 = lane + half * 32;
        float4 bv = ((const float4*)b)[c4];
        float4 gv = ((const float4*)gamma)[c4];
        float4 tv = ((const float4*)beta)[c4];
        float4 mv = ((const float4*)mean)[c4];
        float4 vv = ((const float4*)var)[c4];
        float4 a = half ? acc1 : acc0;
        float4 r;
        float sx = gv.x * rsqrtf(vv.x + 1e-5f);
        float sy = gv.y * rsqrtf(vv.y + 1e-5f);
        float sz = gv.z * rsqrtf(vv.z + 1e-5f);
        float sw = gv.w * rsqrtf(vv.w + 1e-5f);
        r.x = fmaxf(fmaf(a.x + bv.x - mv.x, sx, tv.x), 0.f);
        r.y = fmaxf(fmaf(a.y + bv.y - mv.y, sy, tv.y), 0.f);
        r.z = fmaxf(fmaf(a.z + bv.z - mv.z, sz, tv.z), 0.f);
        r.w = fmaxf(fmaf(a.w + bv.w - mv.w, sw, tv.w), 0.f);
        ((float4*)(out + (size_t)node * DOUT))[c4] = r;
    }
}

// ---------------------------------------------------------------------------
extern "C" void kernel_launch(void* const* d_in, const int* in_sizes, int n_in,
                              void* d_out, int out_size) {
    const float* x      = (const float*)d_in[0];
    const int*   ei     = (const int*)d_in[1];   // int32 (jax x64 disabled)
    const float* W      = (const float*)d_in[2];
    const float* b      = (const float*)d_in[3];
    const float* gamma  = (const float*)d_in[4];
    const float* beta   = (const float*)d_in[5];
    const float* rmean  = (const float*)d_in[6];
    const float* rvar   = (const float*)d_in[7];
    float* out = (float*)d_out;

    int N = in_sizes[0] / DIN;     // 50000
    int E = in_sizes[1] / 2;       // 800000
    const int* src = ei;
    const int* dst = ei + E;
    int nb = (N + 1023) / 1024;

    const int smem_bytes = 2 * STAGE_TOTAL * (int)sizeof(__nv_bfloat16);  // 80 KB
    static bool attr_set = false;
    if (!attr_set) {
        cudaFuncSetAttribute(k_gemm_wmma,
                             cudaFuncAttributeMaxDynamicSharedMemorySize,
                             smem_bytes);
        attr_set = true;
    }

    // 1-3: GEMM prerequisites + degi zero
    k_wt<<<(DIN * DOUT + 255) / 256, 256>>>(W);
    int splitn = MPAD * DIN / 8;
    k_split<<<(splitn + 255) / 256, 256>>>(x, N);
    k_zero<<<(N + 255) / 256, 256>>>(N);

    // 4: GEMM (profiled slot)
    dim3 ggrid(MPAD / 128, DOUT / 128);
    k_gemm_wmma<<<ggrid, 256, smem_bytes>>>();

    // 5-9: CSR build
    k_count<<<(E + 255) / 256, 256>>>(dst, E);
    k_scan1<<<nb, 1024>>>(N);
    k_scan2<<<1, 64>>>(nb);
    k_scan3<<<nb, 1024>>>(N);
    k_fill<<<(E + 255) / 256, 256>>>(src, dst, E);

    // 10: gather + epilogue
    long long nthreads = (long long)N * 32;
    k_node<<<(int)((nthreads + 255) / 256), 256>>>(out, b, gamma, beta,
                                                   rmean, rvar, N);
}

// round 8
// speedup vs baseline: 1.7642x; 1.1177x over previous
#include <cuda_runtime.h>
#include <cuda_bf16.h>
#include <cuda_pipeline.h>
#include <mma.h>
#include <cstdint>

using namespace nvcuda;

#define NNODES 50000
#define MPAD   50048          // 391 * 128
#define EMAX   800000
#define DOUT   256
#define DIN    256

// ---------------------------------------------------------------------------
// Scratch (device globals)
// ---------------------------------------------------------------------------
__device__ float g_h[(size_t)MPAD * DOUT];       // x @ W (fp32, padded rows)
__device__ int   g_degi[NNODES];
__device__ int   g_off[NNODES];
__device__ int   g_cur[NNODES];
__device__ float g_dinv[NNODES];
__device__ int   g_csr[EMAX];
__device__ int   g_bsum[64];
__device__ __nv_bfloat16 g_a_hi[(size_t)MPAD * DIN];
__device__ __nv_bfloat16 g_a_lo[(size_t)MPAD * DIN];
__device__ __nv_bfloat16 g_wt_hi[DOUT * DIN];    // W^T [n][k], k contiguous
__device__ __nv_bfloat16 g_wt_lo[DOUT * DIN];

// ---------------------------------------------------------------------------
// Degree / CSR build
// ---------------------------------------------------------------------------
__global__ void k_zero(int n) {
    int i = blockIdx.x * blockDim.x + threadIdx.x;
    if (i < n) g_degi[i] = 0;
}
__global__ void k_count(const int* __restrict__ dst, int E) {
    int i = blockIdx.x * blockDim.x + threadIdx.x;
    if (i < E) atomicAdd(&g_degi[dst[i]], 1);
}

__global__ __launch_bounds__(1024) void k_scan1(int n) {
    __shared__ int wsum[32];
    int tid = threadIdx.x, lane = tid & 31, wid = tid >> 5;
    int i = blockIdx.x * 1024 + tid;
    int v = (i < n) ? g_degi[i] : 0;
    if (i < n) g_dinv[i] = rsqrtf((float)(v + 1));
    int sc = v;
    #pragma unroll
    for (int o = 1; o < 32; o <<= 1) {
        int t = __shfl_up_sync(0xffffffffu, sc, o);
        if (lane >= o) sc += t;
    }
    if (lane == 31) wsum[wid] = sc;
    __syncthreads();
    if (wid == 0) {
        int s = wsum[lane];
        #pragma unroll
        for (int o = 1; o < 32; o <<= 1) {
            int t = __shfl_up_sync(0xffffffffu, s, o);
            if (lane >= o) s += t;
        }
        wsum[lane] = s;
    }
    __syncthreads();
    int warpoff = (wid > 0) ? wsum[wid - 1] : 0;
    if (i < n) g_off[i] = warpoff + sc - v;
    if (tid == 0) g_bsum[blockIdx.x] = wsum[31];
}

__global__ void k_scan2(int nb) {
    __shared__ int w0tot;
    int t = threadIdx.x, lane = t & 31, wid = t >> 5;
    int v = (t < nb) ? g_bsum[t] : 0;
    int sc = v;
    #pragma unroll
    for (int o = 1; o < 32; o <<= 1) {
        int x = __shfl_up_sync(0xffffffffu, sc, o);
        if (lane >= o) sc += x;
    }
    if (wid == 0 && lane == 31) w0tot = sc;
    __syncthreads();
    int excl = sc - v + (wid ? w0tot : 0);
    if (t < nb) g_bsum[t] = excl;
}

__global__ __launch_bounds__(1024) void k_scan3(int n) {
    int i = blockIdx.x * 1024 + threadIdx.x;
    if (i >= n) return;
    int o = g_off[i] + g_bsum[blockIdx.x];
    g_off[i] = o;
    g_cur[i] = o;
}

__global__ void k_fill(const int* __restrict__ src,
                       const int* __restrict__ dst, int E) {
    int i = blockIdx.x * blockDim.x + threadIdx.x;
    if (i >= E) return;
    int d = dst[i];
    int pos = atomicAdd(&g_cur[d], 1);
    g_csr[pos] = src[i];
}

// ---------------------------------------------------------------------------
// Split prep
// ---------------------------------------------------------------------------
__global__ void k_split(const float* __restrict__ x, int M) {
    int i = blockIdx.x * blockDim.x + threadIdx.x;   // uint4 index (8 bf16)
    int total = MPAD * DIN / 8;
    if (i >= total) return;
    int row = i >> 5;                                 // 32 uint4 per row
    float f[8];
    if (row < M) {
        const float4* p = (const float4*)(x + ((size_t)i << 3));
        float4 v0 = p[0], v1 = p[1];
        f[0] = v0.x; f[1] = v0.y; f[2] = v0.z; f[3] = v0.w;
        f[4] = v1.x; f[5] = v1.y; f[6] = v1.z; f[7] = v1.w;
    } else {
        #pragma unroll
        for (int j = 0; j < 8; j++) f[j] = 0.f;
    }
    uint32_t hi[4], lo[4];
    #pragma unroll
    for (int j = 0; j < 4; j++) {
        __nv_bfloat16 ha = __float2bfloat16_rn(f[j * 2]);
        __nv_bfloat16 hb = __float2bfloat16_rn(f[j * 2 + 1]);
        hi[j] = ((uint32_t)__bfloat16_as_ushort(hb) << 16) | __bfloat16_as_ushort(ha);
        __nv_bfloat16 la = __float2bfloat16_rn(f[j * 2] - __bfloat162float(ha));
        __nv_bfloat16 lb = __float2bfloat16_rn(f[j * 2 + 1] - __bfloat162float(hb));
        lo[j] = ((uint32_t)__bfloat16_as_ushort(lb) << 16) | __bfloat16_as_ushort(la);
    }
    ((uint4*)g_a_hi)[i] = make_uint4(hi[0], hi[1], hi[2], hi[3]);
    ((uint4*)g_a_lo)[i] = make_uint4(lo[0], lo[1], lo[2], lo[3]);
}

__global__ void k_wt(const float* __restrict__ W) {
    int i = blockIdx.x * blockDim.x + threadIdx.x;   // n*256 + k
    if (i >= DIN * DOUT) return;
    int n = i >> 8, k = i & 255;
    float w = W[k * DOUT + n];
    __nv_bfloat16 hi = __float2bfloat16_rn(w);
    g_wt_hi[i] = hi;
    g_wt_lo[i] = __float2bfloat16_rn(w - __bfloat162float(hi));
}

// ---------------------------------------------------------------------------
// WMMA GEMM, double-buffered cp.async mainloop (unchanged from R7).
// ---------------------------------------------------------------------------
#define LDS 40
#define STAGE_ELEMS (128 * LDS)
#define STAGE_TOTAL (4 * STAGE_ELEMS)

__global__ __launch_bounds__(256) void k_gemm_wmma() {
    extern __shared__ __align__(16) __nv_bfloat16 smd[];

    const int tid = threadIdx.x;
    const int w = tid >> 5;
    const int warp_m = w & 3;
    const int warp_n = w >> 2;
    const int Rbase = blockIdx.x * 128;
    const int Nbase = blockIdx.y * 128;

    const int idx0 = tid * 2;
    const int r0 = idx0 >> 2, seg0 = idx0 & 3;
    const int r1 = (idx0 + 1) >> 2, seg1 = (idx0 + 1) & 3;

    auto prefetch = [&](int kc, int stage) {
        __nv_bfloat16* base = smd + stage * STAGE_TOTAL;
        __nv_bfloat16* dA_hi = base;
        __nv_bfloat16* dA_lo = base + STAGE_ELEMS;
        __nv_bfloat16* dB_hi = base + 2 * STAGE_ELEMS;
        __nv_bfloat16* dB_lo = base + 3 * STAGE_ELEMS;
        __pipeline_memcpy_async(dA_hi + r0 * LDS + seg0 * 8,
            (const uint4*)g_a_hi + (size_t)(Rbase + r0) * 32 + kc * 4 + seg0, 16);
        __pipeline_memcpy_async(dA_hi + r1 * LDS + seg1 * 8,
            (const uint4*)g_a_hi + (size_t)(Rbase + r1) * 32 + kc * 4 + seg1, 16);
        __pipeline_memcpy_async(dA_lo + r0 * LDS + seg0 * 8,
            (const uint4*)g_a_lo + (size_t)(Rbase + r0) * 32 + kc * 4 + seg0, 16);
        __pipeline_memcpy_async(dA_lo + r1 * LDS + seg1 * 8,
            (const uint4*)g_a_lo + (size_t)(Rbase + r1) * 32 + kc * 4 + seg1, 16);
        __pipeline_memcpy_async(dB_hi + r0 * LDS + seg0 * 8,
            (const uint4*)g_wt_hi + (size_t)(Nbase + r0) * 32 + kc * 4 + seg0, 16);
        __pipeline_memcpy_async(dB_hi + r1 * LDS + seg1 * 8,
            (const uint4*)g_wt_hi + (size_t)(Nbase + r1) * 32 + kc * 4 + seg1, 16);
        __pipeline_memcpy_async(dB_lo + r0 * LDS + seg0 * 8,
            (const uint4*)g_wt_lo + (size_t)(Nbase + r0) * 32 + kc * 4 + seg0, 16);
        __pipeline_memcpy_async(dB_lo + r1 * LDS + seg1 * 8,
            (const uint4*)g_wt_lo + (size_t)(Nbase + r1) * 32 + kc * 4 + seg1, 16);
        __pipeline_commit();
    };

    wmma::fragment<wmma::accumulator, 16, 16, 16, float> acc[2][4];
    #pragma unroll
    for (int mi = 0; mi < 2; mi++)
        #pragma unroll
        for (int ni = 0; ni < 4; ni++)
            wmma::fill_fragment(acc[mi][ni], 0.0f);

    prefetch(0, 0);

    for (int kc = 0; kc < 8; kc++) {
        if (kc < 7) prefetch(kc + 1, (kc + 1) & 1);
        __pipeline_wait_prior(kc < 7 ? 1 : 0);
        __syncthreads();

        __nv_bfloat16* base = smd + (kc & 1) * STAGE_TOTAL;
        __nv_bfloat16* sA_hi = base;
        __nv_bfloat16* sA_lo = base + STAGE_ELEMS;
        __nv_bfloat16* sB_hi = base + 2 * STAGE_ELEMS;
        __nv_bfloat16* sB_lo = base + 3 * STAGE_ELEMS;

        #pragma unroll
        for (int kk = 0; kk < 32; kk += 16) {
            wmma::fragment<wmma::matrix_a, 16, 16, 16, __nv_bfloat16, wmma::row_major> ah[2], al[2];
            #pragma unroll
            for (int mi = 0; mi < 2; mi++) {
                wmma::load_matrix_sync(ah[mi], sA_hi + (warp_m * 32 + mi * 16) * LDS + kk, LDS);
                wmma::load_matrix_sync(al[mi], sA_lo + (warp_m * 32 + mi * 16) * LDS + kk, LDS);
            }
            wmma::fragment<wmma::matrix_b, 16, 16, 16, __nv_bfloat16, wmma::col_major> bf[4];
            #pragma unroll
            for (int ni = 0; ni < 4; ni++)
                wmma::load_matrix_sync(bf[ni], sB_hi + (warp_n * 64 + ni * 16) * LDS + kk, LDS);
            #pragma unroll
            for (int mi = 0; mi < 2; mi++)
                #pragma unroll
                for (int ni = 0; ni < 4; ni++) {
                    wmma::mma_sync(acc[mi][ni], ah[mi], bf[ni], acc[mi][ni]);
                    wmma::mma_sync(acc[mi][ni], al[mi], bf[ni], acc[mi][ni]);
                }
            #pragma unroll
            for (int ni = 0; ni < 4; ni++)
                wmma::load_matrix_sync(bf[ni], sB_lo + (warp_n * 64 + ni * 16) * LDS + kk, LDS);
            #pragma unroll
            for (int mi = 0; mi < 2; mi++)
                #pragma unroll
                for (int ni = 0; ni < 4; ni++)
                    wmma::mma_sync(acc[mi][ni], ah[mi], bf[ni], acc[mi][ni]);
        }
        __syncthreads();
    }

    #pragma unroll
    for (int mi = 0; mi < 2; mi++) {
        int row = Rbase + warp_m * 32 + mi * 16;
        #pragma unroll
        for (int ni = 0; ni < 4; ni++) {
            int col = Nbase + warp_n * 64 + ni * 16;
            wmma::store_matrix_sync(g_h + (size_t)row * DOUT + col,
                                    acc[mi][ni], DOUT, wmma::mem_row_major);
        }
    }
}

// ---------------------------------------------------------------------------
// Node kernel: one warp per destination node, 4-edge unroll
// ---------------------------------------------------------------------------
#define FMA4(acc, v, s) \
    acc.x = fmaf((v).x, (s), acc.x); acc.y = fmaf((v).y, (s), acc.y); \
    acc.z = fmaf((v).z, (s), acc.z); acc.w = fmaf((v).w, (s), acc.w)

__global__ __launch_bounds__(256) void k_node(float* __restrict__ out,
                                              const float* __restrict__ b,
                                              const float* __restrict__ gamma,
                                              const float* __restrict__ beta,
                                              const float* __restrict__ mean,
                                              const float* __restrict__ var,
                                              int n) {
    int warp = (blockIdx.x * blockDim.x + threadIdx.x) >> 5;
    int lane = threadIdx.x & 31;
    if (warp >= n) return;

    int node = warp;
    int start = g_off[node];
    int end   = start + g_degi[node];

    float4 acc0 = make_float4(0.f, 0.f, 0.f, 0.f);
    float4 acc1 = make_float4(0.f, 0.f, 0.f, 0.f);

    int e = start;
    for (; e + 3 < end; e += 4) {
        int s0 = g_csr[e + 0], s1 = g_csr[e + 1];
        int s2 = g_csr[e + 2], s3 = g_csr[e + 3];
        float w0 = g_dinv[s0], w1 = g_dinv[s1];
        float w2 = g_dinv[s2], w3 = g_dinv[s3];
        const float4* r0 = (const float4*)(g_h + (size_t)s0 * DOUT);
        const float4* r1 = (const float4*)(g_h + (size_t)s1 * DOUT);
        const float4* r2 = (const float4*)(g_h + (size_t)s2 * DOUT);
        const float4* r3 = (const float4*)(g_h + (size_t)s3 * DOUT);
        float4 a0 = __ldg(r0 + lane),      a1 = __ldg(r0 + lane + 32);
        float4 b0 = __ldg(r1 + lane),      b1 = __ldg(r1 + lane + 32);
        float4 c0 = __ldg(r2 + lane),      c1 = __ldg(r2 + lane + 32);
        float4 d0 = __ldg(r3 + lane),      d1 = __ldg(r3 + lane + 32);
        FMA4(acc0, a0, w0); FMA4(acc1, a1, w0);
        FMA4(acc0, b0, w1); FMA4(acc1, b1, w1);
        FMA4(acc0, c0, w2); FMA4(acc1, c1, w2);
        FMA4(acc0, d0, w3); FMA4(acc1, d1, w3);
    }
    for (; e < end; e++) {
        int s0 = g_csr[e];
        float w0 = g_dinv[s0];
        const float4* r0 = (const float4*)(g_h + (size_t)s0 * DOUT);
        float4 a0 = __ldg(r0 + lane), a1 = __ldg(r0 + lane + 32);
        FMA4(acc0, a0, w0); FMA4(acc1, a1, w0);
    }

    float di = g_dinv[node];
    const float4* hr = (const float4*)(g_h + (size_t)node * DOUT);
    float4 h0 = __ldg(hr + lane), h1 = __ldg(hr + lane + 32);
    FMA4(acc0, h0, di); FMA4(acc1, h1, di);
    acc0.x *= di; acc0.y *= di; acc0.z *= di; acc0.w *= di;
    acc1.x *= di; acc1.y *= di; acc1.z *= di; acc1.w *= di;

    #pragma unroll
    for (int half = 0; half < 2; half++) {
        int c4 = lane + half * 32;
        float4 bv = ((const float4*)b)[c4];
        float4 gv = ((const float4*)gamma)[c4];
        float4 tv = ((const float4*)beta)[c4];
        float4 mv = ((const float4*)mean)[c4];
        float4 vv = ((const float4*)var)[c4];
        float4 a = half ? acc1 : acc0;
        float4 r;
        float sx = gv.x * rsqrtf(vv.x + 1e-5f);
        float sy = gv.y * rsqrtf(vv.y + 1e-5f);
        float sz = gv.z * rsqrtf(vv.z + 1e-5f);
        float sw = gv.w * rsqrtf(vv.w + 1e-5f);
        r.x = fmaxf(fmaf(a.x + bv.x - mv.x, sx, tv.x), 0.f);
        r.y = fmaxf(fmaf(a.y + bv.y - mv.y, sy, tv.y), 0.f);
        r.z = fmaxf(fmaf(a.z + bv.z - mv.z, sz, tv.z), 0.f);
        r.w = fmaxf(fmaf(a.w + bv.w - mv.w, sw, tv.w), 0.f);
        ((float4*)(out + (size_t)node * DOUT))[c4] = r;
    }
}

// ---------------------------------------------------------------------------
// Two-stream DAG: CSR build overlaps the GEMM chain.
//   main:  wt -> split -> gemm ----------------+-> node
//   s2:    zero -> count -> scan1/2/3 -> fill -+
// k_gemm_wmma stays the 4th <<<>>> in code order (ncu profile slot).
// ---------------------------------------------------------------------------
extern "C" void kernel_launch(void* const* d_in, const int* in_sizes, int n_in,
                              void* d_out, int out_size) {
    const float* x      = (const float*)d_in[0];
    const int*   ei     = (const int*)d_in[1];   // int32 (jax x64 disabled)
    const float* W      = (const float*)d_in[2];
    const float* b      = (const float*)d_in[3];
    const float* gamma  = (const float*)d_in[4];
    const float* beta   = (const float*)d_in[5];
    const float* rmean  = (const float*)d_in[6];
    const float* rvar   = (const float*)d_in[7];
    float* out = (float*)d_out;

    int N = in_sizes[0] / DIN;     // 50000
    int E = in_sizes[1] / 2;       // 800000
    const int* src = ei;
    const int* dst = ei + E;
    int nb = (N + 1023) / 1024;

    const int smem_bytes = 2 * STAGE_TOTAL * (int)sizeof(__nv_bfloat16);  // 80 KB

    static cudaStream_t s2;
    static cudaEvent_t ev_fork, ev_join;
    static bool init_done = false;
    if (!init_done) {
        cudaFuncSetAttribute(k_gemm_wmma,
                             cudaFuncAttributeMaxDynamicSharedMemorySize,
                             smem_bytes);
        cudaStreamCreateWithFlags(&s2, cudaStreamNonBlocking);
        cudaEventCreateWithFlags(&ev_fork, cudaEventDisableTiming);
        cudaEventCreateWithFlags(&ev_join, cudaEventDisableTiming);
        init_done = true;
    }

    // fork: s2 branches off the origin stream
    cudaEventRecord(ev_fork, 0);
    cudaStreamWaitEvent(s2, ev_fork, 0);

    // main chain: GEMM prerequisites
    k_wt<<<(DIN * DOUT + 255) / 256, 256>>>(W);                    // launch 1
    int splitn = MPAD * DIN / 8;
    k_split<<<(splitn + 255) / 256, 256>>>(x, N);                  // launch 2

    // side chain starts
    k_zero<<<(N + 255) / 256, 256, 0, s2>>>(N);                    // launch 3

    // main chain: GEMM (profile slot 4)
    dim3 ggrid(MPAD / 128, DOUT / 128);
    k_gemm_wmma<<<ggrid, 256, smem_bytes>>>();                     // launch 4

    // side chain: CSR build
    k_count<<<(E + 255) / 256, 256, 0, s2>>>(dst, E);
    k_scan1<<<nb, 1024, 0, s2>>>(N);
    k_scan2<<<1, 64, 0, s2>>>(nb);
    k_scan3<<<nb, 1024, 0, s2>>>(N);
    k_fill<<<(E + 255) / 256, 256, 0, s2>>>(src, dst, E);

    // join: main stream waits for CSR chain
    cudaEventRecord(ev_join, s2);
    cudaStreamWaitEvent(0, ev_join, 0);

    // gather + epilogue
    long long nthreads = (long long)N * 32;
    k_node<<<(int)((nthreads + 255) / 256), 256>>>(out, b, gamma, beta,
                                                   rmean, rvar, N);
}